// round 15
// baseline (speedup 1.0000x reference)
#include <cuda_runtime.h>

#define TLEN 8192
#define TILE 1024
#define NTHR 128              // 2 chunks of 4 outputs per thread
#define GA1  8
#define A1SZ (GA1 + TILE + 8)          // guard + TILE + halo pad
#define GA2  4
#define A2SZ (GA2 + (TILE / 2) + 8)    // guard + TILE/2 compact slots + pad

__constant__ float c_upf[12];
__constant__ float c_dnf[12];

// up-filter coeffs via symmetry uf[j]==uf[11-j]; odd set used for both phases
#define UF1  c_upf[1]
#define UF3  c_upf[3]
#define UF5  c_upf[5]
#define UF7  c_upf[7]
#define UF9  c_upf[9]
#define UF11 c_upf[11]
#define D0 c_dnf[0]
#define D1 c_dnf[1]
#define D2 c_dnf[2]
#define D3 c_dnf[3]
#define D4 c_dnf[4]
#define D5 c_dnf[5]

// act = snake(2*conv): snake(2u) = (2u + k0) - k0*cos(u*a4), a4 = 4*exp(alpha)
__device__ __forceinline__ float snakef(float u, float a4, float k0) {
    return fmaf(-k0, __cosf(u * a4), fmaf(2.0f, u, k0));
}

// Compute 4 (E,O) act pairs, scatter all 12 down-taps of each into acc[0..9]
// (partials of outputs b-6..b+3). Store acc[2..5] (thread t-1) and acc[0..1]
// (thread t-2, compacted); keep acc[6..9] = own outputs.
// xw[j] = x_clamped[m0 + b - 6 + j], j = 0..9
__device__ __forceinline__ void do_chunk(
    const float* __restrict__ xrow, int m0, int b, bool firstWarp0, bool clampLow,
    float a4, float k0, float* A1g, float* A2c, float own[4])
{
    float xw[10];
    if (!firstWarp0) {                   // warp-uniform
        const float* base = xrow + (m0 + b - 6);
        float2 v0 = *(const float2*)base;          // 8B-aligned (b-6 even)
        float4 v1 = *(const float4*)(base + 2);    // 16B-aligned (b-4)
        float4 v2 = *(const float4*)(base + 6);    // 16B-aligned (b)
        xw[0]=v0.x; xw[1]=v0.y;
        xw[2]=v1.x; xw[3]=v1.y; xw[4]=v1.z; xw[5]=v1.w;
        xw[6]=v2.x; xw[7]=v2.y; xw[8]=v2.z; xw[9]=v2.w;
    } else {                             // first block, warp 0: clamp low
        #pragma unroll
        for (int j = 0; j < 10; j++) {
            int g = b - 6 + j;
            xw[j] = xrow[g < 0 ? 0 : g];
        }
    }

    float ev[4], ov[4];
    #pragma unroll
    for (int k = 0; k < 4; k++) {
        float ue =      UF11 * xw[k + 0];
        ue = fmaf(UF9,  xw[k + 1], ue);
        ue = fmaf(UF7,  xw[k + 2], ue);
        ue = fmaf(UF5,  xw[k + 3], ue);
        ue = fmaf(UF3,  xw[k + 4], ue);
        ue = fmaf(UF1,  xw[k + 5], ue);
        float uo =      UF1 * xw[k + 1];
        uo = fmaf(UF3,  xw[k + 2], uo);
        uo = fmaf(UF5,  xw[k + 3], uo);
        uo = fmaf(UF7,  xw[k + 4], uo);
        uo = fmaf(UF9,  xw[k + 5], uo);
        uo = fmaf(UF11, xw[k + 6], uo);
        ev[k] = snakef(ue, a4, k0);
        ov[k] = snakef(uo, a4, k0);
    }
    // first block, tid 0: act indices t<0 clamp to act[0] == E[pair 3]
    if (clampLow) {
        ev[0] = ev[1] = ev[2] = ev[3];
        ov[0] = ov[1] = ov[2] = ev[3];
    }

    // scatter: E[b+j] -> acc[j+di] w/ we={D0,D2,D4,D5,D3,D1};
    //          O[b+j] -> acc[j+1+di] w/ wo={D1,D3,D5,D4,D2,D0}
    float acc[10];
    acc[0] = D0 * ev[0];
    acc[1] = fmaf(D1, ov[0], D2 * ev[0]);
    acc[2] = fmaf(D3, ov[0], D4 * ev[0]);
    acc[3] = fmaf(D5, ov[0], D5 * ev[0]);
    acc[4] = fmaf(D4, ov[0], D3 * ev[0]);
    acc[5] = fmaf(D2, ov[0], D1 * ev[0]);
    acc[6] = D0 * ov[0];
    #pragma unroll
    for (int j = 1; j < 4; j++) {
        acc[j + 0] = fmaf(D0, ev[j], acc[j + 0]);
        acc[j + 1] = fmaf(D2, ev[j], acc[j + 1]);
        acc[j + 2] = fmaf(D4, ev[j], acc[j + 2]);
        acc[j + 3] = fmaf(D5, ev[j], acc[j + 3]);
        acc[j + 4] = fmaf(D3, ev[j], acc[j + 4]);
        acc[j + 5] = fmaf(D1, ev[j], acc[j + 5]);
        acc[j + 1] = fmaf(D1, ov[j], acc[j + 1]);
        acc[j + 2] = fmaf(D3, ov[j], acc[j + 2]);
        acc[j + 3] = fmaf(D5, ov[j], acc[j + 3]);
        acc[j + 4] = fmaf(D4, ov[j], acc[j + 4]);
        acc[j + 5] = fmaf(D2, ov[j], acc[j + 5]);
        acc[j + 6] = D0 * ov[j];
    }

    // cross-thread partials (negative indices land in guard zones, never read)
    *(float4*)(A1g + GA1 + b - 4) = make_float4(acc[2], acc[3], acc[4], acc[5]);
    *(float2*)(A2c + GA2 + 2 * ((b - 6) >> 2)) = make_float2(acc[0], acc[1]);
    own[0] = acc[6]; own[1] = acc[7]; own[2] = acc[8]; own[3] = acc[9];
}

__global__ void __launch_bounds__(NTHR, 16)
act1d_kernel(const float* __restrict__ x,
             const float* __restrict__ alpha,
             const float* __restrict__ beta,
             float* __restrict__ out,
             int nch)
{
    __shared__ __align__(16) float A1g[A1SZ];
    __shared__ __align__(16) float A2c[A2SZ];
    __shared__ float Ehs[6], Ohs[6];

    const int tid = threadIdx.x;
    const int ch  = blockIdx.y;                        // channel directly from grid
    const int row = blockIdx.z * nch + ch;             // (batch, channel) row
    const int m0  = blockIdx.x * TILE;
    const int bA  = 4 * tid;
    const int bB  = (TILE / 2) + 4 * tid;

    const float a4 = 4.0f * __expf(__ldg(alpha + ch));
    const float k0 = 0.5f * __expf(-__ldg(beta + ch));   // == 0.5/(e^b+1e-9) to 1e-9 rel

    const float* xrow = x + (size_t)row * TLEN;
    const bool first = (m0 == 0);
    const bool last  = (m0 + TILE == TLEN);

    float ownA[4], ownB[4];
    do_chunk(xrow, m0, bA, first && tid < 32, first && tid == 0, a4, k0, A1g, A2c, ownA);
    do_chunk(xrow, m0, bB, false,             false,             a4, k0, A1g, A2c, ownB);

    // ---- block-top halo: pairs TILE..TILE+5 -> outputs TILE-6..TILE-1 ----
    if (tid < 32) {
        if (tid < 6) {
            const int q = TILE + tid;
            float xh[7];
            #pragma unroll
            for (int j = 0; j < 7; j++) {
                int g = m0 + q - 6 + j;
                xh[j] = xrow[g > TLEN - 1 ? TLEN - 1 : g];
            }
            float ue =      UF11 * xh[0];
            ue = fmaf(UF9,  xh[1], ue);
            ue = fmaf(UF7,  xh[2], ue);
            ue = fmaf(UF5,  xh[3], ue);
            ue = fmaf(UF3,  xh[4], ue);
            ue = fmaf(UF1,  xh[5], ue);
            float uo =      UF1 * xh[1];
            uo = fmaf(UF3,  xh[2], uo);
            uo = fmaf(UF5,  xh[3], uo);
            uo = fmaf(UF7,  xh[4], uo);
            uo = fmaf(UF9,  xh[5], uo);
            uo = fmaf(UF11, xh[6], uo);
            Ehs[tid] = snakef(ue, a4, k0);
            Ohs[tid] = snakef(uo, a4, k0);
        }
        __syncwarp();
        if (tid == 0) {
            float E0 = Ehs[0], E1 = Ehs[1], E2 = Ehs[2];
            float E3 = Ehs[3], E4 = Ehs[4], E5 = Ehs[5];
            float O0 = Ohs[0], O1 = Ohs[1], O2 = Ohs[2];
            float O3 = Ohs[3], O4 = Ohs[4];
            if (last) {
                // t > 2*TLEN-1 clamps to act[2*TLEN-1] == O of pair TILE+2
                E3 = E4 = E5 = O3 = O4 = Ohs[2];
            }
            // hypothetical thread b=TILE: acc[2..5] = outputs TILE-4..TILE-1
            float p0 = D4*E0 + D2*E1 + D0*E2 + D3*O0 + D1*O1;
            float p1 = D5*E0 + D4*E1 + D2*E2 + D0*E3
                     + D5*O0 + D3*O1 + D1*O2;
            float p2 = D3*E0 + D5*E1 + D4*E2 + D2*E3
                     + D4*O0 + D5*O1 + D3*O2 + D1*O3;
            float p3 = D1*E0 + D3*E1 + D5*E2 + D4*E3
                     + D2*O0 + D4*O1 + D5*O2 + D3*O3;
            *(float4*)(A1g + GA1 + TILE - 4) = make_float4(p0, p1, p2, p3);
            // A2 slots: outputs TILE-6,TILE-5 <- pairs TILE,TILE+1;
            //           outputs TILE-2,TILE-1 <- pairs TILE+4,TILE+5
            float s0 = D0*E0;
            float s1 = D2*E0 + D0*E1 + D1*O0;
            float s2 = D0*E4;
            float s3 = D2*E4 + D0*E5 + D1*O4;
            *(float4*)(A2c + GA2 + TILE/2 - 4) = make_float4(s0, s1, s2, s3);
        }
    }
    __syncthreads();

    // ---- combine partials and store ----
    {
        float4 a1 = *(const float4*)(A1g + GA1 + bA);
        float2 a2p = *(const float2*)(A2c + GA2 + 2 * (bA >> 2));
        float4 r;
        r.x = ownA[0] + a1.x;
        r.y = ownA[1] + a1.y;
        r.z = ownA[2] + a1.z + a2p.x;
        r.w = ownA[3] + a1.w + a2p.y;
        *(float4*)(out + (size_t)row * TLEN + m0 + bA) = r;
    }
    {
        float4 a1 = *(const float4*)(A1g + GA1 + bB);
        float2 a2p = *(const float2*)(A2c + GA2 + 2 * (bB >> 2));
        float4 r;
        r.x = ownB[0] + a1.x;
        r.y = ownB[1] + a1.y;
        r.z = ownB[2] + a1.z + a2p.x;
        r.w = ownB[3] + a1.w + a2p.y;
        *(float4*)(out + (size_t)row * TLEN + m0 + bB) = r;
    }
}

extern "C" void kernel_launch(void* const* d_in, const int* in_sizes, int n_in,
                              void* d_out, int out_size) {
    const float* x     = (const float*)d_in[0];
    const float* alpha = (const float*)d_in[3];
    const float* beta  = (const float*)d_in[4];
    float* out = (float*)d_out;

    // block-uniform filter taps -> constant memory (graph-capturable D2D memcpy)
    cudaMemcpyToSymbolAsync(c_upf, d_in[1], 12 * sizeof(float), 0,
                            cudaMemcpyDeviceToDevice, 0);
    cudaMemcpyToSymbolAsync(c_dnf, d_in[2], 12 * sizeof(float), 0,
                            cudaMemcpyDeviceToDevice, 0);

    const int rows  = in_sizes[0] / TLEN;  // B*C
    const int nch   = in_sizes[3];         // C
    const int batch = rows / nch;          // B

    dim3 grid(TLEN / TILE, nch, batch);    // ch = blockIdx.y (no modulo in-kernel)
    act1d_kernel<<<grid, NTHR>>>(x, alpha, beta, out, nch);
}

// round 16
// speedup vs baseline: 1.0043x; 1.0043x over previous
#include <cuda_runtime.h>

#define TLEN 8192
#define TILE 2048
#define NTHR 256              // 2 chunks of 4 outputs per thread
#define GA1  8
#define A1SZ (GA1 + TILE + 8)          // guard + 2048 + halo pad
#define GA2  4
#define A2SZ (GA2 + (TILE / 2) + 8)    // guard + 1024 compact slots + pad
#define MAXCH 2048

__constant__ float c_upf[12];
__constant__ float c_dnf[12];
__device__ float g_a4[MAXCH];
__device__ float g_k0[MAXCH];

// up-filter coeffs via symmetry uf[j]==uf[11-j]; odd set used for both phases
#define UF1  c_upf[1]
#define UF3  c_upf[3]
#define UF5  c_upf[5]
#define UF7  c_upf[7]
#define UF9  c_upf[9]
#define UF11 c_upf[11]
#define D0 c_dnf[0]
#define D1 c_dnf[1]
#define D2 c_dnf[2]
#define D3 c_dnf[3]
#define D4 c_dnf[4]
#define D5 c_dnf[5]

// act = snake(2*conv): snake(2u) = (2u + k0) - k0*cos(u*a4), a4 = 4*exp(alpha)
__device__ __forceinline__ float snakef(float u, float a4, float k0) {
    return fmaf(-k0, __cosf(u * a4), fmaf(2.0f, u, k0));
}

__global__ void prep_kernel(const float* __restrict__ alpha,
                            const float* __restrict__ beta, int nch) {
    int i = blockIdx.x * blockDim.x + threadIdx.x;
    if (i < nch) {
        g_a4[i] = 4.0f * __expf(alpha[i]);
        g_k0[i] = 0.5f * __expf(-beta[i]);   // == 0.5/(e^b+1e-9) to 1e-9 rel
    }
}

// Compute 4 (E,O) act pairs, scatter all 12 down-taps of each into acc[0..9]
// (partials of outputs b-6..b+3). Store acc[2..5] (thread t-1) and acc[0..1]
// (thread t-2, compacted); keep acc[6..9] = own outputs.
// xw[j] = x_clamped[m0 + b - 6 + j], j = 0..9
__device__ __forceinline__ void do_chunk(
    const float* __restrict__ xrow, int m0, int b, bool firstWarp0, bool clampLow,
    float a4, float k0, float* A1g, float* A2c, float own[4])
{
    float xw[10];
    if (!firstWarp0) {                   // warp-uniform
        const float* base = xrow + (m0 + b - 6);
        float2 v0 = *(const float2*)base;          // 8B-aligned (b-6 even)
        float4 v1 = *(const float4*)(base + 2);    // 16B-aligned (b-4)
        float4 v2 = *(const float4*)(base + 6);    // 16B-aligned (b)
        xw[0]=v0.x; xw[1]=v0.y;
        xw[2]=v1.x; xw[3]=v1.y; xw[4]=v1.z; xw[5]=v1.w;
        xw[6]=v2.x; xw[7]=v2.y; xw[8]=v2.z; xw[9]=v2.w;
    } else {                             // first block, warp 0: clamp low
        #pragma unroll
        for (int j = 0; j < 10; j++) {
            int g = b - 6 + j;
            xw[j] = xrow[g < 0 ? 0 : g];
        }
    }

    float ev[4], ov[4];
    #pragma unroll
    for (int k = 0; k < 4; k++) {
        float ue =      UF11 * xw[k + 0];
        ue = fmaf(UF9,  xw[k + 1], ue);
        ue = fmaf(UF7,  xw[k + 2], ue);
        ue = fmaf(UF5,  xw[k + 3], ue);
        ue = fmaf(UF3,  xw[k + 4], ue);
        ue = fmaf(UF1,  xw[k + 5], ue);
        float uo =      UF1 * xw[k + 1];
        uo = fmaf(UF3,  xw[k + 2], uo);
        uo = fmaf(UF5,  xw[k + 3], uo);
        uo = fmaf(UF7,  xw[k + 4], uo);
        uo = fmaf(UF9,  xw[k + 5], uo);
        uo = fmaf(UF11, xw[k + 6], uo);
        ev[k] = snakef(ue, a4, k0);
        ov[k] = snakef(uo, a4, k0);
    }
    // first block, tid 0: act indices t<0 clamp to act[0] == E[pair 3]
    if (clampLow) {
        ev[0] = ev[1] = ev[2] = ev[3];
        ov[0] = ov[1] = ov[2] = ev[3];
    }

    // scatter: E[b+j] -> acc[j+di] w/ we={D0,D2,D4,D5,D3,D1};
    //          O[b+j] -> acc[j+1+di] w/ wo={D1,D3,D5,D4,D2,D0}
    float acc[10];
    acc[0] = D0 * ev[0];
    acc[1] = fmaf(D1, ov[0], D2 * ev[0]);
    acc[2] = fmaf(D3, ov[0], D4 * ev[0]);
    acc[3] = fmaf(D5, ov[0], D5 * ev[0]);
    acc[4] = fmaf(D4, ov[0], D3 * ev[0]);
    acc[5] = fmaf(D2, ov[0], D1 * ev[0]);
    acc[6] = D0 * ov[0];
    #pragma unroll
    for (int j = 1; j < 4; j++) {
        acc[j + 0] = fmaf(D0, ev[j], acc[j + 0]);
        acc[j + 1] = fmaf(D2, ev[j], acc[j + 1]);
        acc[j + 2] = fmaf(D4, ev[j], acc[j + 2]);
        acc[j + 3] = fmaf(D5, ev[j], acc[j + 3]);
        acc[j + 4] = fmaf(D3, ev[j], acc[j + 4]);
        acc[j + 5] = fmaf(D1, ev[j], acc[j + 5]);
        acc[j + 1] = fmaf(D1, ov[j], acc[j + 1]);
        acc[j + 2] = fmaf(D3, ov[j], acc[j + 2]);
        acc[j + 3] = fmaf(D5, ov[j], acc[j + 3]);
        acc[j + 4] = fmaf(D4, ov[j], acc[j + 4]);
        acc[j + 5] = fmaf(D2, ov[j], acc[j + 5]);
        acc[j + 6] = D0 * ov[j];
    }

    // cross-thread partials (negative indices land in guard zones, never read)
    *(float4*)(A1g + GA1 + b - 4) = make_float4(acc[2], acc[3], acc[4], acc[5]);
    *(float2*)(A2c + GA2 + 2 * ((b - 6) >> 2)) = make_float2(acc[0], acc[1]);
    own[0] = acc[6]; own[1] = acc[7]; own[2] = acc[8]; own[3] = acc[9];
}

__global__ void __launch_bounds__(NTHR, 8)
act1d_kernel(const float* __restrict__ x,
             float* __restrict__ out,
             int nch)
{
    __shared__ __align__(16) float A1g[A1SZ];
    __shared__ __align__(16) float A2c[A2SZ];
    __shared__ float Ehs[6], Ohs[6];

    const int tid = threadIdx.x;
    const int ch  = blockIdx.y;                        // channel directly from grid
    const int row = blockIdx.z * nch + ch;             // (batch, channel) row
    const int m0  = blockIdx.x * TILE;
    const int bA  = 4 * tid;
    const int bB  = 1024 + 4 * tid;

    const float a4 = __ldg(&g_a4[ch]);
    const float k0 = __ldg(&g_k0[ch]);

    const float* xrow = x + (size_t)row * TLEN;
    const bool first = (m0 == 0);
    const bool last  = (m0 + TILE == TLEN);

    float ownA[4], ownB[4];
    do_chunk(xrow, m0, bA, first && tid < 32, first && tid == 0, a4, k0, A1g, A2c, ownA);
    do_chunk(xrow, m0, bB, false,             false,             a4, k0, A1g, A2c, ownB);

    // ---- block-top halo: pairs 2048..2053 -> outputs 2042..2047 ----
    if (tid < 32) {
        if (tid < 6) {
            const int q = TILE + tid;
            float xh[7];
            #pragma unroll
            for (int j = 0; j < 7; j++) {
                int g = m0 + q - 6 + j;
                xh[j] = xrow[g > TLEN - 1 ? TLEN - 1 : g];
            }
            float ue =      UF11 * xh[0];
            ue = fmaf(UF9,  xh[1], ue);
            ue = fmaf(UF7,  xh[2], ue);
            ue = fmaf(UF5,  xh[3], ue);
            ue = fmaf(UF3,  xh[4], ue);
            ue = fmaf(UF1,  xh[5], ue);
            float uo =      UF1 * xh[1];
            uo = fmaf(UF3,  xh[2], uo);
            uo = fmaf(UF5,  xh[3], uo);
            uo = fmaf(UF7,  xh[4], uo);
            uo = fmaf(UF9,  xh[5], uo);
            uo = fmaf(UF11, xh[6], uo);
            Ehs[tid] = snakef(ue, a4, k0);
            Ohs[tid] = snakef(uo, a4, k0);
        }
        __syncwarp();
        // combine split across two lanes to halve the serial tail
        if (tid < 2) {
            float E0 = Ehs[0], E1 = Ehs[1], E2 = Ehs[2];
            float E3 = Ehs[3], E4 = Ehs[4], E5 = Ehs[5];
            float O0 = Ohs[0], O1 = Ohs[1], O2 = Ohs[2];
            float O3 = Ohs[3], O4 = Ohs[4];
            if (last) {
                // t > 16383 clamps to act[16383] == O of pair 2050
                E3 = E4 = E5 = O3 = O4 = Ohs[2];
            }
            if (tid == 0) {
                // hypothetical thread b=2048: acc[2..3] = outputs 2044..2045
                float p0 = D4*E0 + D2*E1 + D0*E2 + D3*O0 + D1*O1;
                float p1 = D5*E0 + D4*E1 + D2*E2 + D0*E3
                         + D5*O0 + D3*O1 + D1*O2;
                *(float2*)(A1g + GA1 + TILE - 4) = make_float2(p0, p1);
                // outputs 2042,2043 <- pairs 2048,2049
                float s0 = D0*E0;
                float s1 = D2*E0 + D0*E1 + D1*O0;
                *(float2*)(A2c + GA2 + TILE/2 - 4) = make_float2(s0, s1);
            } else {
                float p2 = D3*E0 + D5*E1 + D4*E2 + D2*E3
                         + D4*O0 + D5*O1 + D3*O2 + D1*O3;
                float p3 = D1*E0 + D3*E1 + D5*E2 + D4*E3
                         + D2*O0 + D4*O1 + D5*O2 + D3*O3;
                *(float2*)(A1g + GA1 + TILE - 2) = make_float2(p2, p3);
                // outputs 2046,2047 <- pairs 2052,2053
                float s2 = D0*E4;
                float s3 = D2*E4 + D0*E5 + D1*O4;
                *(float2*)(A2c + GA2 + TILE/2 - 2) = make_float2(s2, s3);
            }
        }
    }
    __syncthreads();

    // ---- combine partials and store ----
    {
        float4 a1 = *(const float4*)(A1g + GA1 + bA);
        float2 a2p = *(const float2*)(A2c + GA2 + 2 * (bA >> 2));
        float4 r;
        r.x = ownA[0] + a1.x;
        r.y = ownA[1] + a1.y;
        r.z = ownA[2] + a1.z + a2p.x;
        r.w = ownA[3] + a1.w + a2p.y;
        *(float4*)(out + (size_t)row * TLEN + m0 + bA) = r;
    }
    {
        float4 a1 = *(const float4*)(A1g + GA1 + bB);
        float2 a2p = *(const float2*)(A2c + GA2 + 2 * (bB >> 2));
        float4 r;
        r.x = ownB[0] + a1.x;
        r.y = ownB[1] + a1.y;
        r.z = ownB[2] + a1.z + a2p.x;
        r.w = ownB[3] + a1.w + a2p.y;
        *(float4*)(out + (size_t)row * TLEN + m0 + bB) = r;
    }
}

extern "C" void kernel_launch(void* const* d_in, const int* in_sizes, int n_in,
                              void* d_out, int out_size) {
    const float* x     = (const float*)d_in[0];
    const float* alpha = (const float*)d_in[3];
    const float* beta  = (const float*)d_in[4];
    float* out = (float*)d_out;

    // block-uniform filter taps -> constant memory (graph-capturable D2D memcpy)
    cudaMemcpyToSymbolAsync(c_upf, d_in[1], 12 * sizeof(float), 0,
                            cudaMemcpyDeviceToDevice, 0);
    cudaMemcpyToSymbolAsync(c_dnf, d_in[2], 12 * sizeof(float), 0,
                            cudaMemcpyDeviceToDevice, 0);

    const int rows  = in_sizes[0] / TLEN;  // B*C
    const int nch   = in_sizes[3];         // C
    const int batch = rows / nch;          // B

    // per-channel derived constants (tiny prep kernel, graph-capturable)
    prep_kernel<<<(nch + 255) / 256, 256>>>(alpha, beta, nch);

    dim3 grid(TLEN / TILE, nch, batch);    // ch = blockIdx.y (no modulo in-kernel)
    act1d_kernel<<<grid, NTHR>>>(x, out, nch);
}

// round 17
// speedup vs baseline: 1.0162x; 1.0118x over previous
#include <cuda_runtime.h>

#define TLEN 8192
#define TILE 2048
#define NTHR 256              // 2 chunks of 4 outputs per thread
#define GA1  8
#define A1SZ (GA1 + TILE + 8)          // guard + 2048 + halo pad
#define GA2  4
#define A2SZ (GA2 + (TILE / 2) + 8)    // guard + 1024 compact slots + pad
#define MAXCH 2048

__constant__ float c_upf[12];
__constant__ float c_dnf[12];
__device__ float g_a4[MAXCH];
__device__ float g_k0[MAXCH];

// up-filter coeffs via symmetry uf[j]==uf[11-j]; odd set used for both phases
#define UF1  c_upf[1]
#define UF3  c_upf[3]
#define UF5  c_upf[5]
#define UF7  c_upf[7]
#define UF9  c_upf[9]
#define UF11 c_upf[11]
#define D0 c_dnf[0]
#define D1 c_dnf[1]
#define D2 c_dnf[2]
#define D3 c_dnf[3]
#define D4 c_dnf[4]
#define D5 c_dnf[5]

// act = snake(2*conv): snake(2u) = (2u + k0) - k0*cos(u*a4), a4 = 4*exp(alpha)
__device__ __forceinline__ float snakef(float u, float a4, float k0) {
    return fmaf(-k0, __cosf(u * a4), fmaf(2.0f, u, k0));
}

__global__ void prep_kernel(const float* __restrict__ alpha,
                            const float* __restrict__ beta, int nch) {
    int i = blockIdx.x * blockDim.x + threadIdx.x;
    if (i < nch) {
        g_a4[i] = 4.0f * __expf(alpha[i]);
        g_k0[i] = 0.5f * __expf(-beta[i]);   // == 0.5/(e^b+1e-9) to 1e-9 rel
    }
}

// xw[j] = x_clamped[m0 + b - 6 + j], j = 0..9
__device__ __forceinline__ void do_load(
    const float* __restrict__ xrow, int m0, int b, bool firstWarp0, float xw[10])
{
    if (!firstWarp0) {                   // warp-uniform
        const float* base = xrow + (m0 + b - 6);
        float2 v0 = *(const float2*)base;          // 8B-aligned (b-6 even)
        float4 v1 = *(const float4*)(base + 2);    // 16B-aligned (b-4)
        float4 v2 = *(const float4*)(base + 6);    // 16B-aligned (b)
        xw[0]=v0.x; xw[1]=v0.y;
        xw[2]=v1.x; xw[3]=v1.y; xw[4]=v1.z; xw[5]=v1.w;
        xw[6]=v2.x; xw[7]=v2.y; xw[8]=v2.z; xw[9]=v2.w;
    } else {                             // first block, warp 0: clamp low
        #pragma unroll
        for (int j = 0; j < 10; j++) {
            int g = b - 6 + j;
            xw[j] = xrow[g < 0 ? 0 : g];
        }
    }
}

__device__ __forceinline__ void do_act(
    const float xw[10], bool clampLow, float a4, float k0,
    float ev[4], float ov[4])
{
    #pragma unroll
    for (int k = 0; k < 4; k++) {
        float ue =      UF11 * xw[k + 0];
        ue = fmaf(UF9,  xw[k + 1], ue);
        ue = fmaf(UF7,  xw[k + 2], ue);
        ue = fmaf(UF5,  xw[k + 3], ue);
        ue = fmaf(UF3,  xw[k + 4], ue);
        ue = fmaf(UF1,  xw[k + 5], ue);
        float uo =      UF1 * xw[k + 1];
        uo = fmaf(UF3,  xw[k + 2], uo);
        uo = fmaf(UF5,  xw[k + 3], uo);
        uo = fmaf(UF7,  xw[k + 4], uo);
        uo = fmaf(UF9,  xw[k + 5], uo);
        uo = fmaf(UF11, xw[k + 6], uo);
        ev[k] = snakef(ue, a4, k0);
        ov[k] = snakef(uo, a4, k0);
    }
    // first block, tid 0: act indices t<0 clamp to act[0] == E[pair 3]
    if (clampLow) {
        ev[0] = ev[1] = ev[2] = ev[3];
        ov[0] = ov[1] = ov[2] = ev[3];
    }
}

// scatter: E[b+j] -> acc[j+di] w/ we={D0,D2,D4,D5,D3,D1};
//          O[b+j] -> acc[j+1+di] w/ wo={D1,D3,D5,D4,D2,D0}
__device__ __forceinline__ void do_scatter(
    const float ev[4], const float ov[4], int b,
    float* A1g, float* A2c, float own[4])
{
    float acc[10];
    acc[0] = D0 * ev[0];
    acc[1] = fmaf(D1, ov[0], D2 * ev[0]);
    acc[2] = fmaf(D3, ov[0], D4 * ev[0]);
    acc[3] = fmaf(D5, ov[0], D5 * ev[0]);
    acc[4] = fmaf(D4, ov[0], D3 * ev[0]);
    acc[5] = fmaf(D2, ov[0], D1 * ev[0]);
    acc[6] = D0 * ov[0];
    #pragma unroll
    for (int j = 1; j < 4; j++) {
        acc[j + 0] = fmaf(D0, ev[j], acc[j + 0]);
        acc[j + 1] = fmaf(D2, ev[j], acc[j + 1]);
        acc[j + 2] = fmaf(D4, ev[j], acc[j + 2]);
        acc[j + 3] = fmaf(D5, ev[j], acc[j + 3]);
        acc[j + 4] = fmaf(D3, ev[j], acc[j + 4]);
        acc[j + 5] = fmaf(D1, ev[j], acc[j + 5]);
        acc[j + 1] = fmaf(D1, ov[j], acc[j + 1]);
        acc[j + 2] = fmaf(D3, ov[j], acc[j + 2]);
        acc[j + 3] = fmaf(D5, ov[j], acc[j + 3]);
        acc[j + 4] = fmaf(D4, ov[j], acc[j + 4]);
        acc[j + 5] = fmaf(D2, ov[j], acc[j + 5]);
        acc[j + 6] = D0 * ov[j];
    }

    // cross-thread partials (negative indices land in guard zones, never read)
    *(float4*)(A1g + GA1 + b - 4) = make_float4(acc[2], acc[3], acc[4], acc[5]);
    *(float2*)(A2c + GA2 + 2 * ((b - 6) >> 2)) = make_float2(acc[0], acc[1]);
    own[0] = acc[6]; own[1] = acc[7]; own[2] = acc[8]; own[3] = acc[9];
}

__global__ void __launch_bounds__(NTHR, 8)
act1d_kernel(const float* __restrict__ x,
             float* __restrict__ out,
             int nch)
{
    __shared__ __align__(16) float A1g[A1SZ];
    __shared__ __align__(16) float A2c[A2SZ];
    __shared__ float Ehs[6], Ohs[6];

    const int tid = threadIdx.x;
    const int ch  = blockIdx.y;                        // channel directly from grid
    const int row = blockIdx.z * nch + ch;             // (batch, channel) row
    const int m0  = blockIdx.x * TILE;
    const int bA  = 4 * tid;
    const int bB  = 1024 + 4 * tid;

    const float a4 = __ldg(&g_a4[ch]);
    const float k0 = __ldg(&g_k0[ch]);

    const float* xrow = x + (size_t)row * TLEN;
    const bool first = (m0 == 0);
    const bool last  = (m0 + TILE == TLEN);

    float ownA[4], ownB[4];
    {
        float evA[4], ovA[4], evB[4], ovB[4];
        float xwA[10];
        do_load(xrow, m0, bA, first && tid < 32, xwA);
        do_act(xwA, first && tid == 0, a4, k0, evA, ovA);
        // hoist chunk-B loads here: xwA dead, registers reuse; B's LDG latency
        // overlaps with scatterA's 44 independent FMAs
        float xwB[10];
        do_load(xrow, m0, bB, false, xwB);
        do_scatter(evA, ovA, bA, A1g, A2c, ownA);
        do_act(xwB, false, a4, k0, evB, ovB);
        do_scatter(evB, ovB, bB, A1g, A2c, ownB);
    }

    // ---- block-top halo: pairs 2048..2053 -> outputs 2042..2047 ----
    if (tid < 32) {
        if (tid < 6) {
            const int q = TILE + tid;
            float xh[7];
            #pragma unroll
            for (int j = 0; j < 7; j++) {
                int g = m0 + q - 6 + j;
                xh[j] = xrow[g > TLEN - 1 ? TLEN - 1 : g];
            }
            float ue =      UF11 * xh[0];
            ue = fmaf(UF9,  xh[1], ue);
            ue = fmaf(UF7,  xh[2], ue);
            ue = fmaf(UF5,  xh[3], ue);
            ue = fmaf(UF3,  xh[4], ue);
            ue = fmaf(UF1,  xh[5], ue);
            float uo =      UF1 * xh[1];
            uo = fmaf(UF3,  xh[2], uo);
            uo = fmaf(UF5,  xh[3], uo);
            uo = fmaf(UF7,  xh[4], uo);
            uo = fmaf(UF9,  xh[5], uo);
            uo = fmaf(UF11, xh[6], uo);
            Ehs[tid] = snakef(ue, a4, k0);
            Ohs[tid] = snakef(uo, a4, k0);
        }
        __syncwarp();
        // combine split across two lanes to halve the serial tail
        if (tid < 2) {
            float E0 = Ehs[0], E1 = Ehs[1], E2 = Ehs[2];
            float E3 = Ehs[3], E4 = Ehs[4], E5 = Ehs[5];
            float O0 = Ohs[0], O1 = Ohs[1], O2 = Ohs[2];
            float O3 = Ohs[3], O4 = Ohs[4];
            if (last) {
                // t > 16383 clamps to act[16383] == O of pair 2050
                E3 = E4 = E5 = O3 = O4 = Ohs[2];
            }
            if (tid == 0) {
                // hypothetical thread b=2048: acc[2..3] = outputs 2044..2045
                float p0 = D4*E0 + D2*E1 + D0*E2 + D3*O0 + D1*O1;
                float p1 = D5*E0 + D4*E1 + D2*E2 + D0*E3
                         + D5*O0 + D3*O1 + D1*O2;
                *(float2*)(A1g + GA1 + TILE - 4) = make_float2(p0, p1);
                // outputs 2042,2043 <- pairs 2048,2049
                float s0 = D0*E0;
                float s1 = D2*E0 + D0*E1 + D1*O0;
                *(float2*)(A2c + GA2 + TILE/2 - 4) = make_float2(s0, s1);
            } else {
                float p2 = D3*E0 + D5*E1 + D4*E2 + D2*E3
                         + D4*O0 + D5*O1 + D3*O2 + D1*O3;
                float p3 = D1*E0 + D3*E1 + D5*E2 + D4*E3
                         + D2*O0 + D4*O1 + D5*O2 + D3*O3;
                *(float2*)(A1g + GA1 + TILE - 2) = make_float2(p2, p3);
                // outputs 2046,2047 <- pairs 2052,2053
                float s2 = D0*E4;
                float s3 = D2*E4 + D0*E5 + D1*O4;
                *(float2*)(A2c + GA2 + TILE/2 - 2) = make_float2(s2, s3);
            }
        }
    }
    __syncthreads();

    // ---- combine partials and store ----
    {
        float4 a1 = *(const float4*)(A1g + GA1 + bA);
        float2 a2p = *(const float2*)(A2c + GA2 + 2 * (bA >> 2));
        float4 r;
        r.x = ownA[0] + a1.x;
        r.y = ownA[1] + a1.y;
        r.z = ownA[2] + a1.z + a2p.x;
        r.w = ownA[3] + a1.w + a2p.y;
        *(float4*)(out + (size_t)row * TLEN + m0 + bA) = r;
    }
    {
        float4 a1 = *(const float4*)(A1g + GA1 + bB);
        float2 a2p = *(const float2*)(A2c + GA2 + 2 * (bB >> 2));
        float4 r;
        r.x = ownB[0] + a1.x;
        r.y = ownB[1] + a1.y;
        r.z = ownB[2] + a1.z + a2p.x;
        r.w = ownB[3] + a1.w + a2p.y;
        *(float4*)(out + (size_t)row * TLEN + m0 + bB) = r;
    }
}

extern "C" void kernel_launch(void* const* d_in, const int* in_sizes, int n_in,
                              void* d_out, int out_size) {
    const float* x     = (const float*)d_in[0];
    const float* alpha = (const float*)d_in[3];
    const float* beta  = (const float*)d_in[4];
    float* out = (float*)d_out;

    // block-uniform filter taps -> constant memory (graph-capturable D2D memcpy)
    cudaMemcpyToSymbolAsync(c_upf, d_in[1], 12 * sizeof(float), 0,
                            cudaMemcpyDeviceToDevice, 0);
    cudaMemcpyToSymbolAsync(c_dnf, d_in[2], 12 * sizeof(float), 0,
                            cudaMemcpyDeviceToDevice, 0);

    const int rows  = in_sizes[0] / TLEN;  // B*C
    const int nch   = in_sizes[3];         // C
    const int batch = rows / nch;          // B

    // per-channel derived constants (tiny prep kernel, graph-capturable)
    prep_kernel<<<(nch + 255) / 256, 256>>>(alpha, beta, nch);

    dim3 grid(TLEN / TILE, nch, batch);    // ch = blockIdx.y (no modulo in-kernel)
    act1d_kernel<<<grid, NTHR>>>(x, out, nch);
}